// round 15
// baseline (speedup 1.0000x reference)
#include <cuda_runtime.h>
#include <cuda_fp16.h>
#include <cstdint>

// ---------------------------------------------------------------------------
// TopKRouter via 2-limb fp16 split + mma.sync m16n8k16 (3-product scheme).
// logits = x @ w^T ; softmax ; top-2 (+renorm) ; aux loss.
// out (fp32, 4T+1): [indices(2T) | weights(2T) | aux_loss]
// R15 = R14 (cp.async 4-stage pipeline, prep'd w limbs, LDS-direct frags)
//       + 16 warps (4x4 warp grid, M32xN16/warp) to cover LDS/HMMA latency
//       now that the staging phase no longer barrier-gates all warps.
// ---------------------------------------------------------------------------

#define DIM     2048
#define NEXP    64
#define CTAM    128           // tokens per CTA = 8 x m16
#define KC      32            // K per chunk
#define NCHUNK  (DIM / KC)    // 64
#define THREADS 512           // 16 warps, 4x4 warp grid (M32 x N16 per warp)
#define NSTAGE  4
#define MAXCTA  1024

#define XROWB   160           // x row stride bytes (40 floats)
#define WROWB   80            // w-limb row stride bytes (40 halves)
#define XSTAGE  20480         // 128 * 160
#define WSTAGE  5120          // 64 * 80 per limb
#define STAGEB  (XSTAGE + 2 * WSTAGE)            // 30720
#define SX_OFF(s)     ((s) * STAGEB)
#define SW_OFF(s, l)  ((s) * STAGEB + XSTAGE + (l) * WSTAGE)
#define SMEM_BYTES    (NSTAGE * STAGEB)          // 122880

__device__ unsigned short g_w0[NEXP * DIM];
__device__ unsigned short g_w1[NEXP * DIM];
__device__ float g_P[MAXCTA * NEXP];
__device__ int   g_cnt[MAXCTA * NEXP];
__device__ float g_lse2[MAXCTA];
__device__ int   g_ctr;      // zero-init; self-resetting each launch

__device__ __forceinline__ uint32_t smem_u32(const void* p) {
    uint32_t a;
    asm("{ .reg .u64 t; cvta.to.shared.u64 t, %1; cvt.u32.u64 %0, t; }" : "=r"(a) : "l"(p));
    return a;
}
#define CP16(dst, src) \
    asm volatile("cp.async.cg.shared.global [%0], [%1], 16;" :: "r"(dst), "l"(src) : "memory")
#define CP_COMMIT() asm volatile("cp.async.commit_group;" ::: "memory")
#define CP_WAIT2()  asm volatile("cp.async.wait_group 2;" ::: "memory")

__device__ __forceinline__ void mma16816(float* c, const uint32_t* a, uint32_t b0, uint32_t b1) {
    asm volatile("mma.sync.aligned.m16n8k16.row.col.f32.f16.f16.f32 "
                 "{%0,%1,%2,%3},{%4,%5,%6,%7},{%8,%9},{%0,%1,%2,%3};"
                 : "+f"(c[0]), "+f"(c[1]), "+f"(c[2]), "+f"(c[3])
                 : "r"(a[0]), "r"(a[1]), "r"(a[2]), "r"(a[3]), "r"(b0), "r"(b1));
}
// round-nearest 2-limb fp16 split of a float pair -> packed half2 limbs
__device__ __forceinline__ void split2(float f0, float f1, uint32_t& l0, uint32_t& l1) {
    __half2 h0 = __floats2half2_rn(f0, f1);
    float2 g = __half22float2(h0);
    __half2 h1 = __floats2half2_rn(f0 - g.x, f1 - g.y);
    l0 = *(uint32_t*)&h0;
    l1 = *(uint32_t*)&h1;
}

// ---------------- prep: split gate_w into fp16 limbs ----------------
__global__ void prep_kernel(const float* __restrict__ w) {
    int i = blockIdx.x * 256 + threadIdx.x;       // 64*2048 total
    float f = w[i];
    __half h0 = __float2half_rn(f);
    float r = f - __half2float(h0);
    __half h1 = __float2half_rn(r);
    g_w0[i] = *(unsigned short*)&h0;
    g_w1[i] = *(unsigned short*)&h1;
}

__global__ __launch_bounds__(THREADS, 1)
void router_kernel(const float* __restrict__ x, float* __restrict__ out, int tokens) {
    extern __shared__ char smem[];
    const uint32_t sb = smem_u32(smem);
    const int tid = threadIdx.x, w = tid >> 5, lane = tid & 31;
    const int cta = blockIdx.x, tok0 = cta * CTAM;
    const int mi = w >> 2, ni = w & 3;     // 4x4 warp grid: M32 x N16 per warp
    const int grp = lane >> 2;             // 0..7
    const int kq  = (lane & 3) * 2;        // 0,2,4,6

    __shared__ float sm_m[CTAM];
    __shared__ float sm_is[CTAM];
    __shared__ int   cnt_s[NEXP];
    __shared__ float red_s[4];
    __shared__ int   isLast;

    // issue all cp.async for (stage s, chunk c): x raw + both w-limb tiles
    auto issue_stage = [&](int s, int c) {
        // x: 128 rows x 8 x 16B = 1024 copies over 512 threads
#pragma unroll
        for (int i = 0; i < 2; i++) {
            int idx = i * THREADS + tid;
            int row = idx >> 3, col = idx & 7;
            uint32_t dst = sb + SX_OFF(s) + row * XROWB + col * 16;
            const float* src = x + (size_t)(tok0 + row) * DIM + c * KC + col * 4;
            CP16(dst, src);
        }
        // w limbs: 2 x (64 rows x 4 x 16B) = 512 copies over first 256 threads
        if (tid < 256) {
            int r = tid >> 2, col = tid & 3;
            uint32_t dst0 = sb + SW_OFF(s, 0) + r * WROWB + col * 16;
            uint32_t dst1 = sb + SW_OFF(s, 1) + r * WROWB + col * 16;
            const unsigned short* s0 = g_w0 + (size_t)r * DIM + c * KC + col * 8;
            const unsigned short* s1 = g_w1 + (size_t)r * DIM + c * KC + col * 8;
            CP16(dst0, s0);
            CP16(dst1, s1);
        }
        CP_COMMIT();
    };

    // prologue: stages 0..2
    issue_stage(0, 0);
    issue_stage(1, 1);
    issue_stage(2, 2);

    float acc[2][2][4];                     // [m16 tile][n8 tile][frag]
#pragma unroll
    for (int t = 0; t < 2; t++)
#pragma unroll
        for (int nb = 0; nb < 2; nb++)
#pragma unroll
            for (int j = 0; j < 4; j++) acc[t][nb][j] = 0.f;

#pragma unroll 1
    for (int c = 0; c < NCHUNK; c++) {
        const int s = c & (NSTAGE - 1);
        CP_WAIT2();                 // stage c complete (<=2 younger pending)
        __syncthreads();            // visible to all warps; stage c-1 free
        if (c + NSTAGE - 1 < NCHUNK) issue_stage((c + NSTAGE - 1) & (NSTAGE - 1), c + NSTAGE - 1);

        const uint32_t xbase = sb + SX_OFF(s);
        const uint32_t wb0   = sb + SW_OFF(s, 0);
        const uint32_t wb1   = sb + SW_OFF(s, 1);
#pragma unroll
        for (int ks = 0; ks < 2; ks++) {
            // A raw fragments: rows mi*32 + t*16 + grp(+8), k = ks*16 + kq(+8)
            uint32_t aL0[2][4], aL1[2][4];
#pragma unroll
            for (int t = 0; t < 2; t++) {
                uint32_t abase = xbase + (mi * 32 + t * 16 + grp) * XROWB
                               + (ks * 16 + kq) * 4;
                float2 r0, r1, r2, r3;
                asm volatile("ld.shared.v2.f32 {%0,%1}, [%2];" : "=f"(r0.x), "=f"(r0.y) : "r"(abase));
                asm volatile("ld.shared.v2.f32 {%0,%1}, [%2];" : "=f"(r1.x), "=f"(r1.y) : "r"(abase + 8 * XROWB));
                asm volatile("ld.shared.v2.f32 {%0,%1}, [%2];" : "=f"(r2.x), "=f"(r2.y) : "r"(abase + 32));
                asm volatile("ld.shared.v2.f32 {%0,%1}, [%2];" : "=f"(r3.x), "=f"(r3.y) : "r"(abase + 8 * XROWB + 32));
                split2(r0.x, r0.y, aL0[t][0], aL1[t][0]);
                split2(r1.x, r1.y, aL0[t][1], aL1[t][1]);
                split2(r2.x, r2.y, aL0[t][2], aL1[t][2]);
                split2(r3.x, r3.y, aL0[t][3], aL1[t][3]);
            }
#pragma unroll
            for (int nb = 0; nb < 2; nb++) {
                uint32_t brow = (uint32_t)(ni * 16 + nb * 8 + grp) * WROWB
                              + (ks * 16 + kq) * 2;
                uint32_t b00, b01, b10, b11;
                asm volatile("ld.shared.b32 %0, [%1];" : "=r"(b00) : "r"(wb0 + brow));
                asm volatile("ld.shared.b32 %0, [%1];" : "=r"(b01) : "r"(wb0 + brow + 16));
                asm volatile("ld.shared.b32 %0, [%1];" : "=r"(b10) : "r"(wb1 + brow));
                asm volatile("ld.shared.b32 %0, [%1];" : "=r"(b11) : "r"(wb1 + brow + 16));
#pragma unroll
                for (int t = 0; t < 2; t++) {
                    mma16816(acc[t][nb], aL0[t], b00, b01);   // a0*b0
                    mma16816(acc[t][nb], aL1[t], b00, b01);   // a1*b0
                    mma16816(acc[t][nb], aL0[t], b10, b11);   // a0*b1
                }
            }
        }
    }
    __syncthreads();   // smem free for logits overlay

    // ---- epilogue: accumulators -> smem logits [128][66] ----
    float* L = (float*)smem;
    {
        int cb = ni * 16 + (lane & 3) * 2;
#pragma unroll
        for (int t = 0; t < 2; t++) {
            int r0 = mi * 32 + t * 16 + grp;
#pragma unroll
            for (int nb = 0; nb < 2; nb++) {
                *(float2*)&L[r0 * 66 + cb + nb * 8]       = make_float2(acc[t][nb][0], acc[t][nb][1]);
                *(float2*)&L[(r0 + 8) * 66 + cb + nb * 8] = make_float2(acc[t][nb][2], acc[t][nb][3]);
            }
        }
    }
    if (tid < NEXP) cnt_s[tid] = 0;
    __syncthreads();

    // ---- pass A: per-token top-2, softmax stats, outputs, z ----
    if (tid < CTAM) {
        const int t = tid;
        const float* Lr = &L[t * 66];
        float v1 = -3.402823466e38f, v2 = -3.402823466e38f;
        int i1 = 0, i2 = 0;
#pragma unroll 8
        for (int e = 0; e < NEXP; e++) {
            float l = Lr[e];
            if (l > v1) { v2 = v1; i2 = i1; v1 = l; i1 = e; }
            else if (l > v2) { v2 = l; i2 = e; }
        }
        float S = 0.f;
#pragma unroll 8
        for (int e = 0; e < NEXP; e++) S += __expf(Lr[e] - v1);
        float invS = 1.f / S;
        sm_m[t] = v1; sm_is[t] = invS;

        float lse = v1 + __logf(S);
        float z2 = lse * lse;
#pragma unroll
        for (int o = 16; o > 0; o >>= 1) z2 += __shfl_down_sync(0xffffffffu, z2, o);
        if (lane == 0) red_s[t >> 5] = z2;

        float e2 = __expf(v2 - v1);
        float inv = 1.f / (1.f + e2);
        int gt = tok0 + t;
        out[gt * 2    ] = (float)i1;
        out[gt * 2 + 1] = (float)i2;
        float* wout = out + 2 * tokens;
        wout[gt * 2    ] = inv;
        wout[gt * 2 + 1] = e2 * inv;
        atomicAdd(&cnt_s[i1], 1);
        atomicAdd(&cnt_s[i2], 1);
    }
    __syncthreads();

    // ---- pass B: per-expert softmax-weight partials (fixed order) ----
    if (tid < NEXP) {
        const int e = tid;
        float P = 0.f;
#pragma unroll 8
        for (int t = 0; t < CTAM; t++)
            P += __expf(L[t * 66 + e] - sm_m[t]) * sm_is[t];
        g_P[cta * NEXP + e]   = P;
        g_cnt[cta * NEXP + e] = cnt_s[e];
    }
    if (tid == 0) g_lse2[cta] = ((red_s[0] + red_s[1]) + red_s[2]) + red_s[3];

    // ---- last CTA finalizes (deterministic fixed-order reduction) ----
    __threadfence();
    __syncthreads();
    if (tid == 0) {
        int prev = atomicAdd(&g_ctr, 1);
        isLast = (prev == (int)gridDim.x - 1);
    }
    __syncthreads();
    if (!isLast) return;

    {
        const int nCta = (int)gridDim.x;     // 128
        __shared__ float sP2[2][NEXP];
        __shared__ float sC2[2][NEXP];
        __shared__ float sZ2[128];
        if (tid < 128) {
            int s2 = tid >> 6, e = tid & 63;
            float P = 0.f, C = 0.f;
            for (int c2 = s2; c2 < nCta; c2 += 2) {   // fixed per-slice order
                P += g_P[c2 * NEXP + e];
                C += (float)g_cnt[c2 * NEXP + e];
            }
            sP2[s2][e] = P; sC2[s2][e] = C;
        }
        if (tid < 128) sZ2[tid] = (tid < nCta) ? g_lse2[tid] : 0.f;
        __syncthreads();
        if (tid == 0) {
            float tsum = 0.f;
            for (int e = 0; e < NEXP; e++) {
                float P = sP2[0][e] + sP2[1][e];
                float C = sC2[0][e] + sC2[1][e];
                tsum += (C / (float)(tokens * 2)) * (P / (float)tokens);
            }
            float z = 0.f;
            for (int i = 0; i < 128; i++) z += sZ2[i];
            out[4 * tokens] = 0.01f * ((float)NEXP * tsum) + 0.001f * (z / (float)tokens);
            g_ctr = 0;   // self-reset for next launch / graph replay
        }
    }
}

extern "C" void kernel_launch(void* const* d_in, const int* in_sizes, int n_in,
                              void* d_out, int out_size) {
    const float* x = (const float*)d_in[0];
    const float* w = (const float*)d_in[1];
    float* out = (float*)d_out;
    int tokens = in_sizes[0] / DIM;              // 16384
    int nCta   = tokens / CTAM;                  // 128 (exact)
    cudaFuncSetAttribute(router_kernel, cudaFuncAttributeMaxDynamicSharedMemorySize, SMEM_BYTES);
    prep_kernel<<<(NEXP * DIM) / 256, 256>>>(w);
    router_kernel<<<nCta, THREADS, SMEM_BYTES>>>(x, out, tokens);
}

// round 16
// speedup vs baseline: 1.1172x; 1.1172x over previous
#include <cuda_runtime.h>
#include <cuda_fp16.h>
#include <cstdint>

// ---------------------------------------------------------------------------
// TopKRouter via 2-limb fp16 split + mma.sync m16n8k16 (3-product scheme).
// logits = x @ w^T ; softmax ; top-2 (+renorm) ; aux loss.
// x: [T=16384, D=2048] fp32, w: [E=64, D=2048] fp32.
// out (fp32, 4T+1): [indices(2T) | weights(2T) | aux_loss]
// R16 = R6 + MMA REORDER: per k-step, load all A/B fragments, then issue
// MMAs product-major across all 8 independent accumulators -> no
// back-to-back same-accumulator HMMAs (RAW stalls ~24-32cyc each were the
// invariant binder across every prior variant).
// ---------------------------------------------------------------------------

#define DIM     2048
#define NEXP    64
#define CTAM    128           // tokens per CTA = 8 x m16
#define KC      32            // K per chunk
#define NCHUNK  (DIM / KC)    // 64
#define THREADS 256           // 8 warps, 4x2 warp grid (M32 x N32 per warp)
#define MAXCTA  1024

#define PADH    40            // halves per smem row (80 B) -> conflict-free ldmatrix
#define ROWB    (PADH * 2)    // 80
// per buffer: A0,A1 (128*80=10240 B each), B0,B1 (64*80=5120 B each)
#define SA_OFF(buf, l)  ((buf) * 30720 + (l) * 10240)
#define SB_OFF(buf, l)  ((buf) * 30720 + 20480 + (l) * 5120)
#define SMEM_BYTES      61440

__device__ float g_P[MAXCTA * NEXP];
__device__ int   g_cnt[MAXCTA * NEXP];
__device__ float g_lse2[MAXCTA];
__device__ int   g_ctr;      // zero-init; self-resetting each launch

__device__ __forceinline__ uint32_t smem_u32(const void* p) {
    uint32_t a;
    asm("{ .reg .u64 t; cvta.to.shared.u64 t, %1; cvt.u32.u64 %0, t; }" : "=r"(a) : "l"(p));
    return a;
}
__device__ __forceinline__ void ldsm4(uint32_t* r, uint32_t a) {
    asm volatile("ldmatrix.sync.aligned.m8n8.x4.shared.b16 {%0,%1,%2,%3}, [%4];"
                 : "=r"(r[0]), "=r"(r[1]), "=r"(r[2]), "=r"(r[3]) : "r"(a));
}
__device__ __forceinline__ void mma16816(float* c, const uint32_t* a, uint32_t b0, uint32_t b1) {
    asm volatile("mma.sync.aligned.m16n8k16.row.col.f32.f16.f16.f32 "
                 "{%0,%1,%2,%3},{%4,%5,%6,%7},{%8,%9},{%0,%1,%2,%3};"
                 : "+f"(c[0]), "+f"(c[1]), "+f"(c[2]), "+f"(c[3])
                 : "r"(a[0]), "r"(a[1]), "r"(a[2]), "r"(a[3]), "r"(b0), "r"(b1));
}
// round-nearest 2-limb fp16 split of a float pair -> packed half2 limbs
__device__ __forceinline__ void split2(float f0, float f1, uint32_t& l0, uint32_t& l1) {
    __half2 h0 = __floats2half2_rn(f0, f1);
    float2 g = __half22float2(h0);
    __half2 h1 = __floats2half2_rn(f0 - g.x, f1 - g.y);
    l0 = *(uint32_t*)&h0;
    l1 = *(uint32_t*)&h1;
}

__global__ __launch_bounds__(THREADS, 1)
void router_kernel(const float* __restrict__ x, const float* __restrict__ wgl,
                   float* __restrict__ out, int tokens) {
    extern __shared__ char smem[];
    const uint32_t sb = smem_u32(smem);
    const int tid = threadIdx.x, w = tid >> 5, lane = tid & 31;
    const int cta = blockIdx.x, tok0 = cta * CTAM;
    const int mi = w >> 1, ni = w & 1;     // 4x2 warp grid: M32 x N32 per warp

    __shared__ float sm_m[CTAM];
    __shared__ float sm_is[CTAM];
    __shared__ int   cnt_s[NEXP];
    __shared__ float red_s[4];
    __shared__ int   isLast;

    // ---- GEMM mainloop (double-buffered, 1 sync/chunk) ----
    const float4* xg = (const float4*)(x + (size_t)tok0 * DIM);
    // x staging: 4 float4/thread; idx = i*256+tid: row = idx/8 (128), c4 = idx%8
    int rowx[4], c4x[4];
    float4 xv[4];
#pragma unroll
    for (int i = 0; i < 4; i++) {
        int idx = i * THREADS + tid;
        rowx[i] = idx >> 3; c4x[i] = idx & 7;
        xv[i] = xg[(size_t)rowx[i] * (DIM / 4) + c4x[i]];
    }
    // w staging: 2 float4/thread: expert = tid/4, float4 base = (tid&3)*2
    const int er = tid >> 2, kg4 = (tid & 3) * 2;
    float4 wf[2];
#pragma unroll
    for (int i = 0; i < 2; i++)
        wf[i] = ((const float4*)wgl)[(size_t)er * (DIM / 4) + kg4 + i];

    float acc[2][4][4];                     // [m-tile][n8][frag]
#pragma unroll
    for (int t = 0; t < 2; t++)
#pragma unroll
        for (int nb = 0; nb < 4; nb++)
#pragma unroll
            for (int j = 0; j < 4; j++) acc[t][nb][j] = 0.f;

    // ldmatrix lane address components (byte offsets within a tile)
    const uint32_t aOff = (uint32_t)(mi * 32 + (lane & 15)) * ROWB + (lane >> 4) * 16;
    const uint32_t bOff = (uint32_t)(ni * 32 + (lane & 7) + ((lane >> 4) & 1) * 8) * ROWB
                        + ((lane >> 3) & 1) * 16;

    for (int c = 0; c < NCHUNK; c++) {
        const int buf = c & 1;
        // store x limbs
#pragma unroll
        for (int i = 0; i < 4; i++) {
            uint32_t p0, p1, q0, q1;
            split2(xv[i].x, xv[i].y, p0, q0);
            split2(xv[i].z, xv[i].w, p1, q1);
            uint32_t off = (uint32_t)rowx[i] * ROWB + c4x[i] * 8;
            *(uint2*)(smem + SA_OFF(buf, 0) + off) = make_uint2(p0, p1);
            *(uint2*)(smem + SA_OFF(buf, 1) + off) = make_uint2(q0, q1);
        }
        // split + store w limbs (8 bytes of halves per float4)
#pragma unroll
        for (int i = 0; i < 2; i++) {
            uint32_t p0, p1, q0, q1;
            split2(wf[i].x, wf[i].y, p0, q0);
            split2(wf[i].z, wf[i].w, p1, q1);
            uint32_t off = (uint32_t)er * ROWB + (kg4 + i) * 8;
            *(uint2*)(smem + SB_OFF(buf, 0) + off) = make_uint2(p0, p1);
            *(uint2*)(smem + SB_OFF(buf, 1) + off) = make_uint2(q0, q1);
        }
        __syncthreads();
        // prefetch next chunk
        if (c + 1 < NCHUNK) {
            int k4 = (c + 1) * (KC / 4);
#pragma unroll
            for (int i = 0; i < 4; i++)
                xv[i] = xg[(size_t)rowx[i] * (DIM / 4) + k4 + c4x[i]];
#pragma unroll
            for (int i = 0; i < 2; i++)
                wf[i] = ((const float4*)wgl)[(size_t)er * (DIM / 4) + k4 + kg4 + i];
        }
        // compute: 3 limb products (00, 10, 01); 11 dropped (~6e-9 rel).
        // MMAs issued PRODUCT-MAJOR across all 8 accs: same-acc updates are
        // separated by 8 independent MMAs (64 cyc > HMMA latency).
        const uint32_t a0b = sb + SA_OFF(buf, 0) + aOff;
        const uint32_t a1b = sb + SA_OFF(buf, 1) + aOff;
        const uint32_t b0b = sb + SB_OFF(buf, 0) + bOff;
        const uint32_t b1b = sb + SB_OFF(buf, 1) + bOff;
#pragma unroll
        for (int ks = 0; ks < 2; ks++) {
            uint32_t af0[2][4], af1[2][4], b0f[2][4], b1f[2][4];
#pragma unroll
            for (int t = 0; t < 2; t++) {
                ldsm4(af0[t], a0b + t * 16 * ROWB + ks * 32);
                ldsm4(af1[t], a1b + t * 16 * ROWB + ks * 32);
            }
#pragma unroll
            for (int nb2 = 0; nb2 < 2; nb2++) {
                ldsm4(b0f[nb2], b0b + nb2 * 16 * ROWB + ks * 32);
                ldsm4(b1f[nb2], b1b + nb2 * 16 * ROWB + ks * 32);
            }
            // product 1: a0 * b0  (8 MMAs, all distinct accumulators)
#pragma unroll
            for (int t = 0; t < 2; t++)
#pragma unroll
                for (int nb2 = 0; nb2 < 2; nb2++) {
                    mma16816(acc[t][nb2 * 2    ], af0[t], b0f[nb2][0], b0f[nb2][1]);
                    mma16816(acc[t][nb2 * 2 + 1], af0[t], b0f[nb2][2], b0f[nb2][3]);
                }
            // product 2: a1 * b0
#pragma unroll
            for (int t = 0; t < 2; t++)
#pragma unroll
                for (int nb2 = 0; nb2 < 2; nb2++) {
                    mma16816(acc[t][nb2 * 2    ], af1[t], b0f[nb2][0], b0f[nb2][1]);
                    mma16816(acc[t][nb2 * 2 + 1], af1[t], b0f[nb2][2], b0f[nb2][3]);
                }
            // product 3: a0 * b1
#pragma unroll
            for (int t = 0; t < 2; t++)
#pragma unroll
                for (int nb2 = 0; nb2 < 2; nb2++) {
                    mma16816(acc[t][nb2 * 2    ], af0[t], b1f[nb2][0], b1f[nb2][1]);
                    mma16816(acc[t][nb2 * 2 + 1], af0[t], b1f[nb2][2], b1f[nb2][3]);
                }
        }
    }
    __syncthreads();   // smem free for logits overlay

    // ---- epilogue: accumulators -> smem logits [128][66] ----
    float* L = (float*)smem;
    {
        int cb = ni * 32 + (lane & 3) * 2;
#pragma unroll
        for (int t = 0; t < 2; t++) {
            int r0 = mi * 32 + t * 16 + (lane >> 2);
#pragma unroll
            for (int nb = 0; nb < 4; nb++) {
                *(float2*)&L[r0 * 66 + cb + nb * 8]       = make_float2(acc[t][nb][0], acc[t][nb][1]);
                *(float2*)&L[(r0 + 8) * 66 + cb + nb * 8] = make_float2(acc[t][nb][2], acc[t][nb][3]);
            }
        }
    }
    if (tid < NEXP) cnt_s[tid] = 0;
    __syncthreads();

    // ---- pass A: per-token top-2, softmax stats, outputs, z ----
    if (tid < CTAM) {
        const int t = tid;
        const float* Lr = &L[t * 66];
        float v1 = -3.402823466e38f, v2 = -3.402823466e38f;
        int i1 = 0, i2 = 0;
#pragma unroll 8
        for (int e = 0; e < NEXP; e++) {
            float l = Lr[e];
            if (l > v1) { v2 = v1; i2 = i1; v1 = l; i1 = e; }
            else if (l > v2) { v2 = l; i2 = e; }
        }
        float S = 0.f;
#pragma unroll 8
        for (int e = 0; e < NEXP; e++) S += __expf(Lr[e] - v1);
        float invS = 1.f / S;
        sm_m[t] = v1; sm_is[t] = invS;

        float lse = v1 + __logf(S);
        float z2 = lse * lse;
#pragma unroll
        for (int o = 16; o > 0; o >>= 1) z2 += __shfl_down_sync(0xffffffffu, z2, o);
        if (lane == 0) red_s[t >> 5] = z2;

        float e2 = __expf(v2 - v1);
        float inv = 1.f / (1.f + e2);
        int gt = tok0 + t;
        out[gt * 2    ] = (float)i1;
        out[gt * 2 + 1] = (float)i2;
        float* wout = out + 2 * tokens;
        wout[gt * 2    ] = inv;
        wout[gt * 2 + 1] = e2 * inv;
        atomicAdd(&cnt_s[i1], 1);
        atomicAdd(&cnt_s[i2], 1);
    }
    __syncthreads();

    // ---- pass B: per-expert softmax-weight partials (fixed order) ----
    if (tid < NEXP) {
        const int e = tid;
        float P = 0.f;
#pragma unroll 8
        for (int t = 0; t < CTAM; t++)
            P += __expf(L[t * 66 + e] - sm_m[t]) * sm_is[t];
        g_P[cta * NEXP + e]   = P;
        g_cnt[cta * NEXP + e] = cnt_s[e];
    }
    if (tid == 0) g_lse2[cta] = ((red_s[0] + red_s[1]) + red_s[2]) + red_s[3];

    // ---- last CTA finalizes (deterministic fixed-order reduction) ----
    __threadfence();
    __syncthreads();
    if (tid == 0) {
        int prev = atomicAdd(&g_ctr, 1);
        isLast = (prev == (int)gridDim.x - 1);
    }
    __syncthreads();
    if (!isLast) return;

    {
        const int nCta = (int)gridDim.x;     // 128
        __shared__ float sP2[2][NEXP];
        __shared__ float sC2[2][NEXP];
        __shared__ float sZ2[128];
        if (tid < 128) {
            int s2 = tid >> 6, e = tid & 63;
            float P = 0.f, C = 0.f;
            for (int c2 = s2; c2 < nCta; c2 += 2) {   // fixed per-slice order
                P += g_P[c2 * NEXP + e];
                C += (float)g_cnt[c2 * NEXP + e];
            }
            sP2[s2][e] = P; sC2[s2][e] = C;
        }
        if (tid < 128) sZ2[tid] = (tid < nCta) ? g_lse2[tid] : 0.f;
        __syncthreads();
        if (tid == 0) {
            float tsum = 0.f;
            for (int e = 0; e < NEXP; e++) {
                float P = sP2[0][e] + sP2[1][e];
                float C = sC2[0][e] + sC2[1][e];
                tsum += (C / (float)(tokens * 2)) * (P / (float)tokens);
            }
            float z = 0.f;
            for (int i = 0; i < 128; i++) z += sZ2[i];
            out[4 * tokens] = 0.01f * ((float)NEXP * tsum) + 0.001f * (z / (float)tokens);
            g_ctr = 0;   // self-reset for next launch / graph replay
        }
    }
}

extern "C" void kernel_launch(void* const* d_in, const int* in_sizes, int n_in,
                              void* d_out, int out_size) {
    const float* x = (const float*)d_in[0];
    const float* w = (const float*)d_in[1];
    float* out = (float*)d_out;
    int tokens = in_sizes[0] / DIM;              // 16384
    int nCta   = tokens / CTAM;                  // 128 (exact)
    cudaFuncSetAttribute(router_kernel, cudaFuncAttributeMaxDynamicSharedMemorySize, SMEM_BYTES);
    router_kernel<<<nCta, THREADS, SMEM_BYTES>>>(x, w, out, tokens);
}